// round 1
// baseline (speedup 1.0000x reference)
#include <cuda_runtime.h>
#include <cstdint>

#define LL 1024
#define BB 2048
#define KK 16
#define BPC 14                 // batch elements per CTA
#define NTHREADS (BPC * 16)    // 224 threads = 7 warps

__device__ __forceinline__ float ex2f(float x) {
    float y; asm("ex2.approx.f32 %0, %1;" : "=f"(y) : "f"(x)); return y;
}
__device__ __forceinline__ float rcpf(float x) {
    float y; asm("rcp.approx.f32 %0, %1;" : "=f"(y) : "f"(x)); return y;
}
// sigmoid(x) = 1/(1+exp(-x)); exp via ex2 (2 ulp), rcp.approx (~1 ulp)
__device__ __forceinline__ float sigf(float x) {
    return rcpf(1.0f + ex2f(-1.4426950408889634f * x));
}
// tanh(x) = 2*sigmoid(2x) - 1
__device__ __forceinline__ float mytanh(float x) {
    return fmaf(2.0f, sigf(2.0f * x), -1.0f);
}

__global__ void __launch_bounds__(NTHREADS, 1) rnn_fused_kernel(
    const float* __restrict__ u_in,   // [L,B,4]
    const float* __restrict__ x_in,   // [L,B,4]
    const float* __restrict__ pu_W1, const float* __restrict__ pu_b1,
    const float* __restrict__ pu_W2, const float* __restrict__ pu_b2,
    const float* __restrict__ px_W1, const float* __restrict__ px_b1,
    const float* __restrict__ px_W2, const float* __restrict__ px_b2,
    const float* __restrict__ W_ih,  const float* __restrict__ b_ih,
    const float* __restrict__ W_hh,  const float* __restrict__ b_hh,
    const float* __restrict__ dec_W1, const float* __restrict__ dec_b1,
    const float* __restrict__ dec_W2, const float* __restrict__ dec_b2,
    float* __restrict__ out_x,        // [L,B,4]
    float* __restrict__ out_h)        // [L,B,16]
{
    // ---- shared weights (transposed for conflict-free lane-indexed reads) ----
    __shared__ __align__(16) float spu1[4][16];    // spu1[i][c]  = pu_W1[c][i]
    __shared__ __align__(16) float spx1[4][16];
    __shared__ __align__(16) float spu2[16][16];   // spu2[k][c]  = pu_W2[c][k]
    __shared__ __align__(16) float spx2[16][16];
    __shared__ __align__(16) float sd1t[16][32];   // sd1t[k][j]  = dec_W1[j][k]
    __shared__ __align__(16) float sd2[4][32];     // sd2[o][h]   = dec_W2[o][h]
    // ---- per-batch activation staging ----
    __shared__ __align__(16) float s_uin[BPC][4];
    __shared__ __align__(16) float s_xin[BPC][4];
    __shared__ __align__(16) float s_t1[BPC][16];
    __shared__ __align__(16) float s_t2[BPC][16];
    __shared__ __align__(16) float s_ue[BPC][16];
    __shared__ __align__(16) float s_xe[BPC][16];
    __shared__ __align__(16) float s_h[BPC][16];

    const int tid  = threadIdx.x;
    const int lane = tid & 15;   // channel 0..15
    const int g    = tid >> 4;   // group (batch slot) within CTA

    // stage shared weights cooperatively
    for (int i = tid; i < 64;  i += NTHREADS) { spu1[i & 3][i >> 2]  = pu_W1[i];  spx1[i & 3][i >> 2]  = px_W1[i]; }
    for (int i = tid; i < 256; i += NTHREADS) { spu2[i & 15][i >> 4] = pu_W2[i];  spx2[i & 15][i >> 4] = px_W2[i]; }
    for (int i = tid; i < 512; i += NTHREADS) { sd1t[i & 15][i >> 4] = dec_W1[i]; }
    for (int i = tid; i < 128; i += NTHREADS) { sd2[i >> 5][i & 31]  = dec_W2[i]; }

    const int b       = blockIdx.x * BPC + g;
    const bool active = (b < BB);
    const int bb      = active ? b : (BB - 1);

    // ---- per-lane register weights (loop-invariant, fully unrolled) ----
    float wr[32], wz[32], wn[32];
#pragma unroll
    for (int k = 0; k < 32; k++) {
        wr[k] = W_ih[(0  + lane) * 32 + k];
        wz[k] = W_ih[(16 + lane) * 32 + k];
        wn[k] = W_ih[(32 + lane) * 32 + k];
    }
    float vr[16], vz[16], vn[16];
#pragma unroll
    for (int k = 0; k < 16; k++) {
        vr[k] = W_hh[(0  + lane) * 16 + k];
        vz[k] = W_hh[(16 + lane) * 16 + k];
        vn[k] = W_hh[(32 + lane) * 16 + k];
    }
    const float bxr = b_ih[lane], bxz = b_ih[16 + lane], bxn = b_ih[32 + lane];
    const float bhr = b_hh[lane], bhz = b_hh[16 + lane], bhn = b_hh[32 + lane];
    const float bu1 = pu_b1[lane], bu2 = pu_b2[lane];
    const float bv1 = px_b1[lane], bv2 = px_b2[lane];
    const float db1_0 = dec_b1[2 * lane], db1_1 = dec_b1[2 * lane + 1];
    const float db2   = (lane < 4) ? dec_b2[lane] : 0.0f;

    s_h[g][lane] = 0.0f;
    __syncthreads();

    // prefetch step-0 inputs
    float4 nu = make_float4(0.f, 0.f, 0.f, 0.f), nx = nu;
    if (lane == 0) nu = *(const float4*)(u_in + (size_t)bb * 4);
    if (lane == 1) nx = *(const float4*)(x_in + (size_t)bb * 4);

    for (int l = 0; l < LL; l++) {
        if (lane == 0) *(float4*)s_uin[g] = nu;
        if (lane == 1) *(float4*)s_xin[g] = nx;
        __syncwarp();
        // prefetch next step (hides DRAM latency behind the full step's FMAs)
        if (l + 1 < LL) {
            const size_t off = ((size_t)(l + 1) * BB + bb) * 4;
            if (lane == 0) nu = *(const float4*)(u_in + off);
            if (lane == 1) nx = *(const float4*)(x_in + off);
        }

        // ---- preprocess layer 1 ----
        float t1 = bu1, t2 = bv1;
#pragma unroll
        for (int i = 0; i < 4; i++) {
            t1 = fmaf(spu1[i][lane], s_uin[g][i], t1);
            t2 = fmaf(spx1[i][lane], s_xin[g][i], t2);
        }
        t1 = mytanh(t1); t2 = mytanh(t2);
        s_t1[g][lane] = t1; s_t2[g][lane] = t2;
        __syncwarp();

        // ---- preprocess layer 2 ----
        float ue = bu2, xe = bv2;
#pragma unroll
        for (int k = 0; k < 16; k++) {
            ue = fmaf(spu2[k][lane], s_t1[g][k], ue);
            xe = fmaf(spx2[k][lane], s_t2[g][k], xe);
        }
        ue = mytanh(ue); xe = mytanh(xe);
        s_ue[g][lane] = ue; s_xe[g][lane] = xe;
        __syncwarp();

        // ---- input gates: gx = W_ih @ [u_emb; x_emb] + b_ih ----
        float xr = bxr, xz = bxz, xn = bxn;
#pragma unroll
        for (int k = 0; k < 16; k++) {
            const float v = s_ue[g][k];
            xr = fmaf(wr[k], v, xr); xz = fmaf(wz[k], v, xz); xn = fmaf(wn[k], v, xn);
        }
#pragma unroll
        for (int k = 0; k < 16; k++) {
            const float v = s_xe[g][k];
            xr = fmaf(wr[16 + k], v, xr); xz = fmaf(wz[16 + k], v, xz); xn = fmaf(wn[16 + k], v, xn);
        }

        // ---- hidden gates: gh = W_hh @ h + b_hh ----
        float hr = bhr, hz = bhz, hn = bhn;
#pragma unroll
        for (int k = 0; k < 16; k++) {
            const float v = s_h[g][k];
            hr = fmaf(vr[k], v, hr); hz = fmaf(vz[k], v, hz); hn = fmaf(vn[k], v, hn);
        }

        const float h_old = s_h[g][lane];
        // h_seq[l] = pre-update hidden (h0 first, last dropped)
        if (active) out_h[((size_t)l * BB + bb) * 16 + lane] = h_old;

        const float r = sigf(xr + hr);
        const float z = sigf(xz + hz);
        const float n = mytanh(fmaf(r, hn, xn));
        const float h_new = fmaf(z, h_old - n, n);   // (1-z)*n + z*h

        __syncwarp();                 // everyone done reading old s_h
        s_h[g][lane] = h_new;
        __syncwarp();

        // ---- decoder: d = tanh(dec_W1 @ h_new + b1); x = dec_W2 @ d + b2 ----
        float d0 = db1_0, d1 = db1_1;
#pragma unroll
        for (int k = 0; k < 16; k++) {
            const float v = s_h[g][k];
            const float2 w = *(const float2*)&sd1t[k][2 * lane];
            d0 = fmaf(w.x, v, d0); d1 = fmaf(w.y, v, d1);
        }
        d0 = mytanh(d0); d1 = mytanh(d1);

        const float2 w0 = *(const float2*)&sd2[0][2 * lane];
        const float2 w1 = *(const float2*)&sd2[1][2 * lane];
        const float2 w2 = *(const float2*)&sd2[2][2 * lane];
        const float2 w3 = *(const float2*)&sd2[3][2 * lane];
        float p0 = fmaf(d0, w0.x, d1 * w0.y);
        float p1 = fmaf(d0, w1.x, d1 * w1.y);
        float p2 = fmaf(d0, w2.x, d1 * w2.y);
        float p3 = fmaf(d0, w3.x, d1 * w3.y);
        // butterfly reduce over the 16-lane group (xor<=8 stays in-half)
#pragma unroll
        for (int m = 8; m >= 1; m >>= 1) {
            p0 += __shfl_xor_sync(0xffffffffu, p0, m);
            p1 += __shfl_xor_sync(0xffffffffu, p1, m);
            p2 += __shfl_xor_sync(0xffffffffu, p2, m);
            p3 += __shfl_xor_sync(0xffffffffu, p3, m);
        }
        if (active && lane < 4) {
            const float v = (lane == 0) ? p0 : (lane == 1) ? p1 : (lane == 2) ? p2 : p3;
            out_x[((size_t)l * BB + bb) * 4 + lane] = v + db2;
        }
    }
}

extern "C" void kernel_launch(void* const* d_in, const int* in_sizes, int n_in,
                              void* d_out, int out_size) {
    const float* u_in   = (const float*)d_in[0];
    const float* x_in   = (const float*)d_in[1];
    const float* pu_W1  = (const float*)d_in[2];
    const float* pu_b1  = (const float*)d_in[3];
    const float* pu_W2  = (const float*)d_in[4];
    const float* pu_b2  = (const float*)d_in[5];
    const float* px_W1  = (const float*)d_in[6];
    const float* px_b1  = (const float*)d_in[7];
    const float* px_W2  = (const float*)d_in[8];
    const float* px_b2  = (const float*)d_in[9];
    const float* W_ih   = (const float*)d_in[10];
    const float* b_ih   = (const float*)d_in[11];
    const float* W_hh   = (const float*)d_in[12];
    const float* b_hh   = (const float*)d_in[13];
    const float* dec_W1 = (const float*)d_in[14];
    const float* dec_b1 = (const float*)d_in[15];
    const float* dec_W2 = (const float*)d_in[16];
    const float* dec_b2 = (const float*)d_in[17];

    float* out_x = (float*)d_out;                        // [L,B,4]
    float* out_h = (float*)d_out + (size_t)LL * BB * 4;  // [L,B,16]

    const int grid = (BB + BPC - 1) / BPC;  // 147 CTAs
    rnn_fused_kernel<<<grid, NTHREADS>>>(
        u_in, x_in, pu_W1, pu_b1, pu_W2, pu_b2,
        px_W1, px_b1, px_W2, px_b2,
        W_ih, b_ih, W_hh, b_hh,
        dec_W1, dec_b1, dec_W2, dec_b2,
        out_x, out_h);
}

// round 2
// speedup vs baseline: 1.2491x; 1.2491x over previous
#include <cuda_runtime.h>
#include <cstdint>

#define L_ 1024
#define B_ 2048
#define NE (L_ * B_)

// scratch: input-to-hidden gate projections [L*B][48], and final hidden [B][16]
__device__ float g_gates[(size_t)NE * 48];
__device__ float g_hlast[B_ * 16];

__device__ __forceinline__ float ex2f(float x) {
    float y; asm("ex2.approx.f32 %0, %1;" : "=f"(y) : "f"(x)); return y;
}
__device__ __forceinline__ float rcpf(float x) {
    float y; asm("rcp.approx.f32 %0, %1;" : "=f"(y) : "f"(x)); return y;
}
__device__ __forceinline__ float sigf(float x) {
    return rcpf(1.0f + ex2f(-1.4426950408889634f * x));
}
__device__ __forceinline__ float mytanh(float x) {
    return fmaf(2.0f, sigf(2.0f * x), -1.0f);
}

// ============================================================================
// K1: pre-MLPs + W_ih projection for every (l,b) — fully parallel, FMA-bound
// ============================================================================
__global__ void __launch_bounds__(256) k1_gates(
    const float* __restrict__ u_in, const float* __restrict__ x_in,
    const float* __restrict__ pu_W1, const float* __restrict__ pu_b1,
    const float* __restrict__ pu_W2, const float* __restrict__ pu_b2,
    const float* __restrict__ px_W1, const float* __restrict__ px_b1,
    const float* __restrict__ px_W2, const float* __restrict__ px_b2,
    const float* __restrict__ W_ih, const float* __restrict__ b_ih)
{
    __shared__ __align__(16) float s_pu1[64], s_px1[64];
    __shared__ __align__(16) float s_pu2[256], s_px2[256];
    __shared__ __align__(16) float s_wT[32][48];   // s_wT[d][g] = W_ih[g][d]
    __shared__ __align__(16) float s_bih[48];
    __shared__ float s_bu1[16], s_bu2[16], s_bx1[16], s_bx2[16];

    const int tid = threadIdx.x;
    for (int i = tid; i < 64;  i += 256) { s_pu1[i] = pu_W1[i]; s_px1[i] = px_W1[i]; }
    for (int i = tid; i < 256; i += 256) { s_pu2[i] = pu_W2[i]; s_px2[i] = px_W2[i]; }
    for (int i = tid; i < 1536; i += 256) { s_wT[i & 31][i >> 5] = W_ih[i]; }
    if (tid < 48) s_bih[tid] = b_ih[tid];
    if (tid < 16) { s_bu1[tid] = pu_b1[tid]; s_bu2[tid] = pu_b2[tid];
                    s_bx1[tid] = px_b1[tid]; s_bx2[tid] = px_b2[tid]; }
    __syncthreads();

    const int e = blockIdx.x * 256 + tid;   // NE divisible by 256
    const float4 u = *(const float4*)(u_in + (size_t)e * 4);
    const float4 x = *(const float4*)(x_in + (size_t)e * 4);

    // preprocess layer 1
    float t1[16], t2[16];
#pragma unroll
    for (int c = 0; c < 16; c++) {
        const float4 wu = *(const float4*)&s_pu1[c * 4];
        const float4 wx = *(const float4*)&s_px1[c * 4];
        t1[c] = mytanh(fmaf(wu.x, u.x, fmaf(wu.y, u.y, fmaf(wu.z, u.z, fmaf(wu.w, u.w, s_bu1[c])))));
        t2[c] = mytanh(fmaf(wx.x, x.x, fmaf(wx.y, x.y, fmaf(wx.z, x.z, fmaf(wx.w, x.w, s_bx1[c])))));
    }
    // preprocess layer 2
    float ue[16], xe[16];
#pragma unroll
    for (int c = 0; c < 16; c++) {
        float a0 = s_bu2[c], b0 = s_bx2[c], a1 = 0.f, b1 = 0.f;
#pragma unroll
        for (int k = 0; k < 8; k++)  { a0 = fmaf(s_pu2[c * 16 + k], t1[k], a0);
                                       b0 = fmaf(s_px2[c * 16 + k], t2[k], b0); }
#pragma unroll
        for (int k = 8; k < 16; k++) { a1 = fmaf(s_pu2[c * 16 + k], t1[k], a1);
                                       b1 = fmaf(s_px2[c * 16 + k], t2[k], b1); }
        ue[c] = mytanh(a0 + a1);
        xe[c] = mytanh(b0 + b1);
    }
    // gx = W_ih @ [ue; xe] + b_ih  — 48 independent accumulators
    float acc[48];
#pragma unroll
    for (int i = 0; i < 48; i++) acc[i] = s_bih[i];
#pragma unroll
    for (int k = 0; k < 16; k++) {
        const float a = ue[k];
#pragma unroll
        for (int i = 0; i < 48; i++) acc[i] = fmaf(s_wT[k][i], a, acc[i]);
    }
#pragma unroll
    for (int k = 0; k < 16; k++) {
        const float a = xe[k];
#pragma unroll
        for (int i = 0; i < 48; i++) acc[i] = fmaf(s_wT[16 + k][i], a, acc[i]);
    }
    float* gp = g_gates + (size_t)e * 48;
#pragma unroll
    for (int i = 0; i < 12; i++)
        *(float4*)(gp + i * 4) = make_float4(acc[i*4], acc[i*4+1], acc[i*4+2], acc[i*4+3]);
}

// ============================================================================
// K2: GRU recurrence only — short per-step chain, gates prefetched 2 ahead
// ============================================================================
#define BPC 14
#define NT2 (BPC * 16)

__global__ void __launch_bounds__(NT2, 1) k2_recur(
    const float* __restrict__ W_hh, const float* __restrict__ b_hh,
    float* __restrict__ out_h)
{
    __shared__ __align__(16) float s_h[BPC][16];
    const int tid = threadIdx.x, lane = tid & 15, g = tid >> 4;
    const int b = blockIdx.x * BPC + g;
    const bool active = (b < B_);
    const int bb = active ? b : (B_ - 1);

    float vr[16], vz[16], vn[16];
#pragma unroll
    for (int k = 0; k < 16; k++) {
        vr[k] = W_hh[lane * 16 + k];
        vz[k] = W_hh[(16 + lane) * 16 + k];
        vn[k] = W_hh[(32 + lane) * 16 + k];
    }
    const float bhr = b_hh[lane], bhz = b_hh[16 + lane], bhn = b_hh[32 + lane];

    s_h[g][lane] = 0.f;
    __syncthreads();

    // 2-deep prefetch ring for the input gates
    float pr[2], pz[2], pn[2];
#pragma unroll
    for (int l = 0; l < 2; l++) {
        const float* gp = g_gates + ((size_t)l * B_ + bb) * 48;
        pr[l] = gp[lane]; pz[l] = gp[16 + lane]; pn[l] = gp[32 + lane];
    }

    float h_new = 0.f;
    for (int l = 0; l < L_; l++) {
        const int s = l & 1;
        const float xr = pr[s], xz = pz[s], xn = pn[s];
        if (l + 2 < L_) {
            const float* gp = g_gates + ((size_t)(l + 2) * B_ + bb) * 48;
            pr[s] = gp[lane]; pz[s] = gp[16 + lane]; pn[s] = gp[32 + lane];
        }
        float hh[16];
        *(float4*)&hh[0]  = ((const float4*)s_h[g])[0];
        *(float4*)&hh[4]  = ((const float4*)s_h[g])[1];
        *(float4*)&hh[8]  = ((const float4*)s_h[g])[2];
        *(float4*)&hh[12] = ((const float4*)s_h[g])[3];
        const float h_old = hh[0];  // placeholder; real value below
        (void)h_old;
        const float h_prev = s_h[g][lane];

        float r0 = bhr, r1 = 0.f, z0 = bhz, z1 = 0.f, n0 = bhn, n1 = 0.f;
#pragma unroll
        for (int k = 0; k < 8; k++)  { r0 = fmaf(vr[k], hh[k], r0);
                                       z0 = fmaf(vz[k], hh[k], z0);
                                       n0 = fmaf(vn[k], hh[k], n0); }
#pragma unroll
        for (int k = 8; k < 16; k++) { r1 = fmaf(vr[k], hh[k], r1);
                                       z1 = fmaf(vz[k], hh[k], z1);
                                       n1 = fmaf(vn[k], hh[k], n1); }
        if (active) out_h[((size_t)l * B_ + bb) * 16 + lane] = h_prev;

        const float r = sigf(xr + (r0 + r1));
        const float z = sigf(xz + (z0 + z1));
        const float n = mytanh(fmaf(r, n0 + n1, xn));
        h_new = fmaf(z, h_prev - n, n);

        __syncwarp();
        s_h[g][lane] = h_new;
        __syncwarp();
    }
    if (active) g_hlast[(size_t)bb * 16 + lane] = h_new;
}

// ============================================================================
// K3: decoder MLP on every post-step hidden — fully parallel
// h_all[l] = out_h[l+1] for l < L-1, else g_hlast
// ============================================================================
__global__ void __launch_bounds__(256) k3_dec(
    const float* __restrict__ dec_W1, const float* __restrict__ dec_b1,
    const float* __restrict__ dec_W2, const float* __restrict__ dec_b2,
    const float* __restrict__ out_h, float* __restrict__ out_x)
{
    __shared__ __align__(16) float s_d1[512];   // dec_W1 [32][16] row-major
    __shared__ __align__(16) float s_d2[128];   // dec_W2 [4][32] row-major
    __shared__ float s_b1[32];
    __shared__ float s_b2[4];
    const int tid = threadIdx.x;
    for (int i = tid; i < 512; i += 256) s_d1[i] = dec_W1[i];
    if (tid < 128) s_d2[tid] = dec_W2[tid];
    if (tid < 32)  s_b1[tid] = dec_b1[tid];
    if (tid < 4)   s_b2[tid] = dec_b2[tid];
    __syncthreads();

    const int e = blockIdx.x * 256 + tid;
    const int l = e >> 11;          // / B_
    const int b = e & (B_ - 1);
    const float* hp = (l < L_ - 1) ? (out_h + ((size_t)e + B_) * 16)
                                   : (g_hlast + (size_t)b * 16);
    float hh[16];
    *(float4*)&hh[0]  = *(const float4*)(hp + 0);
    *(float4*)&hh[4]  = *(const float4*)(hp + 4);
    *(float4*)&hh[8]  = *(const float4*)(hp + 8);
    *(float4*)&hh[12] = *(const float4*)(hp + 12);

    float o0 = s_b2[0], o1 = s_b2[1], o2 = s_b2[2], o3 = s_b2[3];
#pragma unroll
    for (int j = 0; j < 32; j++) {
        float a0 = s_b1[j], a1 = 0.f;
#pragma unroll
        for (int k = 0; k < 8; k++)  a0 = fmaf(s_d1[j * 16 + k], hh[k], a0);
#pragma unroll
        for (int k = 8; k < 16; k++) a1 = fmaf(s_d1[j * 16 + k], hh[k], a1);
        const float d = mytanh(a0 + a1);
        o0 = fmaf(s_d2[j],      d, o0);
        o1 = fmaf(s_d2[32 + j], d, o1);
        o2 = fmaf(s_d2[64 + j], d, o2);
        o3 = fmaf(s_d2[96 + j], d, o3);
    }
    *(float4*)(out_x + (size_t)e * 4) = make_float4(o0, o1, o2, o3);
}

// ============================================================================
extern "C" void kernel_launch(void* const* d_in, const int* in_sizes, int n_in,
                              void* d_out, int out_size) {
    const float* u_in   = (const float*)d_in[0];
    const float* x_in   = (const float*)d_in[1];
    const float* pu_W1  = (const float*)d_in[2];
    const float* pu_b1  = (const float*)d_in[3];
    const float* pu_W2  = (const float*)d_in[4];
    const float* pu_b2  = (const float*)d_in[5];
    const float* px_W1  = (const float*)d_in[6];
    const float* px_b1  = (const float*)d_in[7];
    const float* px_W2  = (const float*)d_in[8];
    const float* px_b2  = (const float*)d_in[9];
    const float* W_ih   = (const float*)d_in[10];
    const float* b_ih   = (const float*)d_in[11];
    const float* W_hh   = (const float*)d_in[12];
    const float* b_hh   = (const float*)d_in[13];
    const float* dec_W1 = (const float*)d_in[14];
    const float* dec_b1 = (const float*)d_in[15];
    const float* dec_W2 = (const float*)d_in[16];
    const float* dec_b2 = (const float*)d_in[17];

    float* out_x = (float*)d_out;                          // [L,B,4]
    float* out_h = (float*)d_out + (size_t)L_ * B_ * 4;    // [L,B,16]

    k1_gates<<<NE / 256, 256>>>(u_in, x_in, pu_W1, pu_b1, pu_W2, pu_b2,
                                px_W1, px_b1, px_W2, px_b2, W_ih, b_ih);
    k2_recur<<<(B_ + BPC - 1) / BPC, NT2>>>(W_hh, b_hh, out_h);
    k3_dec<<<NE / 256, 256>>>(dec_W1, dec_b1, dec_W2, dec_b2, out_h, out_x);
}

// round 3
// speedup vs baseline: 2.0265x; 1.6224x over previous
#include <cuda_runtime.h>
#include <cstdint>

#define L_ 1024
#define B_ 2048
#define NE (L_ * B_)

// scratch: input-to-hidden gate projections [L*B][48], and final hidden [B][16]
__device__ float g_gates[(size_t)NE * 48];
__device__ float g_hlast[B_ * 16];

__device__ __forceinline__ float ex2f(float x) {
    float y; asm("ex2.approx.f32 %0, %1;" : "=f"(y) : "f"(x)); return y;
}
__device__ __forceinline__ float rcpf(float x) {
    float y; asm("rcp.approx.f32 %0, %1;" : "=f"(y) : "f"(x)); return y;
}
__device__ __forceinline__ float sigf(float x) {
    return rcpf(1.0f + ex2f(-1.4426950408889634f * x));
}
__device__ __forceinline__ float mytanh(float x) {
    return fmaf(2.0f, sigf(2.0f * x), -1.0f);
}

// ============================================================================
// K1: pre-MLPs + W_ih projection for every (l,b) — parallel, FMA-bound
// (all SMEM reads vectorized to LDS.128 to stay off the LSU limiter)
// ============================================================================
__global__ void __launch_bounds__(256) k1_gates(
    const float* __restrict__ u_in, const float* __restrict__ x_in,
    const float* __restrict__ pu_W1, const float* __restrict__ pu_b1,
    const float* __restrict__ pu_W2, const float* __restrict__ pu_b2,
    const float* __restrict__ px_W1, const float* __restrict__ px_b1,
    const float* __restrict__ px_W2, const float* __restrict__ px_b2,
    const float* __restrict__ W_ih, const float* __restrict__ b_ih)
{
    __shared__ __align__(16) float s_pu1[64], s_px1[64];
    __shared__ __align__(16) float s_pu2[256], s_px2[256];
    __shared__ __align__(16) float s_wT[32][48];   // s_wT[d][g] = W_ih[g][d]
    __shared__ __align__(16) float s_bih[48];
    __shared__ float s_bu1[16], s_bu2[16], s_bx1[16], s_bx2[16];

    const int tid = threadIdx.x;
    for (int i = tid; i < 64;  i += 256) { s_pu1[i] = pu_W1[i]; s_px1[i] = px_W1[i]; }
    for (int i = tid; i < 256; i += 256) { s_pu2[i] = pu_W2[i]; s_px2[i] = px_W2[i]; }
    for (int i = tid; i < 1536; i += 256) { s_wT[i & 31][i >> 5] = W_ih[i]; }
    if (tid < 48) s_bih[tid] = b_ih[tid];
    if (tid < 16) { s_bu1[tid] = pu_b1[tid]; s_bu2[tid] = pu_b2[tid];
                    s_bx1[tid] = px_b1[tid]; s_bx2[tid] = px_b2[tid]; }
    __syncthreads();

    const int e = blockIdx.x * 256 + tid;   // NE divisible by 256
    const float4 u = *(const float4*)(u_in + (size_t)e * 4);
    const float4 x = *(const float4*)(x_in + (size_t)e * 4);

    // preprocess layer 1
    float t1[16], t2[16];
#pragma unroll
    for (int c = 0; c < 16; c++) {
        const float4 wu = *(const float4*)&s_pu1[c * 4];
        const float4 wx = *(const float4*)&s_px1[c * 4];
        t1[c] = mytanh(fmaf(wu.x, u.x, fmaf(wu.y, u.y, fmaf(wu.z, u.z, fmaf(wu.w, u.w, s_bu1[c])))));
        t2[c] = mytanh(fmaf(wx.x, x.x, fmaf(wx.y, x.y, fmaf(wx.z, x.z, fmaf(wx.w, x.w, s_bx1[c])))));
    }
    // preprocess layer 2 (float4 weight loads)
    float ue[16], xe[16];
#pragma unroll
    for (int c = 0; c < 16; c++) {
        float a0 = s_bu2[c], b0 = s_bx2[c], a1 = 0.f, b1 = 0.f;
#pragma unroll
        for (int q = 0; q < 2; q++) {
            const float4 wa = *(const float4*)&s_pu2[c * 16 + q * 4];
            const float4 wb = *(const float4*)&s_pu2[c * 16 + 8 + q * 4];
            const float4 va = *(const float4*)&s_px2[c * 16 + q * 4];
            const float4 vb = *(const float4*)&s_px2[c * 16 + 8 + q * 4];
            a0 = fmaf(wa.x, t1[q*4+0], fmaf(wa.y, t1[q*4+1], fmaf(wa.z, t1[q*4+2], fmaf(wa.w, t1[q*4+3], a0))));
            a1 = fmaf(wb.x, t1[8+q*4+0], fmaf(wb.y, t1[8+q*4+1], fmaf(wb.z, t1[8+q*4+2], fmaf(wb.w, t1[8+q*4+3], a1))));
            b0 = fmaf(va.x, t2[q*4+0], fmaf(va.y, t2[q*4+1], fmaf(va.z, t2[q*4+2], fmaf(va.w, t2[q*4+3], b0))));
            b1 = fmaf(vb.x, t2[8+q*4+0], fmaf(vb.y, t2[8+q*4+1], fmaf(vb.z, t2[8+q*4+2], fmaf(vb.w, t2[8+q*4+3], b1))));
        }
        ue[c] = mytanh(a0 + a1);
        xe[c] = mytanh(b0 + b1);
    }
    // gx = W_ih @ [ue; xe] + b_ih  — 48 accumulators, float4 weight loads
    float4 acc[12];
#pragma unroll
    for (int i = 0; i < 12; i++) acc[i] = *(const float4*)&s_bih[i * 4];
#pragma unroll
    for (int k = 0; k < 32; k++) {
        const float a = (k < 16) ? ue[k] : xe[k - 16];
#pragma unroll
        for (int i = 0; i < 12; i++) {
            const float4 w = *(const float4*)&s_wT[k][i * 4];
            acc[i].x = fmaf(w.x, a, acc[i].x);
            acc[i].y = fmaf(w.y, a, acc[i].y);
            acc[i].z = fmaf(w.z, a, acc[i].z);
            acc[i].w = fmaf(w.w, a, acc[i].w);
        }
    }
    float* gp = g_gates + (size_t)e * 48;
#pragma unroll
    for (int i = 0; i < 12; i++)
        *(float4*)(gp + i * 4) = acc[i];
}

// ============================================================================
// K2: GRU recurrence — 8-deep register-ring gate prefetch, double-buffered h
// ============================================================================
#define BPC 14
#define NT2 (BPC * 16)

__global__ void __launch_bounds__(NT2, 1) k2_recur(
    const float* __restrict__ W_hh, const float* __restrict__ b_hh,
    float* __restrict__ out_h)
{
    __shared__ __align__(16) float s_h[2][BPC][16];
    const int tid = threadIdx.x, lane = tid & 15, g = tid >> 4;
    const int b = blockIdx.x * BPC + g;
    const bool active = (b < B_);
    const int bb = active ? b : (B_ - 1);

    float vr[16], vz[16], vn[16];
#pragma unroll
    for (int k = 0; k < 16; k++) {
        vr[k] = W_hh[lane * 16 + k];
        vz[k] = W_hh[(16 + lane) * 16 + k];
        vn[k] = W_hh[(32 + lane) * 16 + k];
    }
    const float bhr = b_hh[lane], bhz = b_hh[16 + lane], bhn = b_hh[32 + lane];

    s_h[0][g][lane] = 0.f;
    s_h[1][g][lane] = 0.f;
    __syncthreads();

    const float* gb = g_gates + (size_t)bb * 48;
    const size_t lstride = (size_t)B_ * 48;

    // 8-deep gate prefetch ring (block-structured so indices stay static)
    float cr[8], cz[8], cn[8], nr[8], nz[8], nn[8];
#pragma unroll
    for (int j = 0; j < 8; j++) {
        const float* gp = gb + (size_t)j * lstride;
        cr[j] = gp[lane]; cz[j] = gp[16 + lane]; cn[j] = gp[32 + lane];
    }

    float h_new = 0.f;
    for (int blk = 0; blk < L_ / 8; blk++) {
#pragma unroll
        for (int j = 0; j < 8; j++) {
            const int l = blk * 8 + j;
            // prefetch the matching slot of the NEXT block (consumed 8 steps later)
            if (blk < L_ / 8 - 1) {
                const float* gp = gb + (size_t)(l + 8) * lstride;
                nr[j] = gp[lane]; nz[j] = gp[16 + lane]; nn[j] = gp[32 + lane];
            }
            const int p = j & 1;            // blk*8 is even, so (l&1)==(j&1)
            float hh[16];
            *(float4*)&hh[0]  = ((const float4*)s_h[p][g])[0];
            *(float4*)&hh[4]  = ((const float4*)s_h[p][g])[1];
            *(float4*)&hh[8]  = ((const float4*)s_h[p][g])[2];
            *(float4*)&hh[12] = ((const float4*)s_h[p][g])[3];
            const float h_prev = hh[lane];
            if (active) out_h[((size_t)l * B_ + bb) * 16 + lane] = h_prev;

            float r0 = bhr, r1 = 0.f, z0 = bhz, z1 = 0.f, n0 = bhn, n1 = 0.f;
#pragma unroll
            for (int k = 0; k < 8; k++)  { r0 = fmaf(vr[k], hh[k], r0);
                                           z0 = fmaf(vz[k], hh[k], z0);
                                           n0 = fmaf(vn[k], hh[k], n0); }
#pragma unroll
            for (int k = 8; k < 16; k++) { r1 = fmaf(vr[k], hh[k], r1);
                                           z1 = fmaf(vz[k], hh[k], z1);
                                           n1 = fmaf(vn[k], hh[k], n1); }
            const float r = sigf(cr[j] + (r0 + r1));
            const float z = sigf(cz[j] + (z0 + z1));
            const float n = mytanh(fmaf(r, n0 + n1, cn[j]));
            h_new = fmaf(z, h_prev - n, n);

            s_h[1 - p][g][lane] = h_new;
            __syncwarp();
        }
#pragma unroll
        for (int j = 0; j < 8; j++) { cr[j] = nr[j]; cz[j] = nz[j]; cn[j] = nn[j]; }
    }
    if (active) g_hlast[(size_t)bb * 16 + lane] = h_new;
}

// ============================================================================
// K3: decoder MLP on every post-step hidden — fully parallel
// h_all[l] = out_h[l+1] for l < L-1, else g_hlast
// ============================================================================
__global__ void __launch_bounds__(256) k3_dec(
    const float* __restrict__ dec_W1, const float* __restrict__ dec_b1,
    const float* __restrict__ dec_W2, const float* __restrict__ dec_b2,
    const float* __restrict__ out_h, float* __restrict__ out_x)
{
    __shared__ __align__(16) float s_d1[512];   // dec_W1 [32][16] row-major
    __shared__ __align__(16) float s_d2[128];   // dec_W2 [4][32] row-major
    __shared__ float s_b1[32];
    __shared__ float s_b2[4];
    const int tid = threadIdx.x;
    for (int i = tid; i < 512; i += 256) s_d1[i] = dec_W1[i];
    if (tid < 128) s_d2[tid] = dec_W2[tid];
    if (tid < 32)  s_b1[tid] = dec_b1[tid];
    if (tid < 4)   s_b2[tid] = dec_b2[tid];
    __syncthreads();

    const int e = blockIdx.x * 256 + tid;
    const int l = e >> 11;          // / B_
    const int b = e & (B_ - 1);
    const float* hp = (l < L_ - 1) ? (out_h + ((size_t)e + B_) * 16)
                                   : (g_hlast + (size_t)b * 16);
    float hh[16];
    *(float4*)&hh[0]  = *(const float4*)(hp + 0);
    *(float4*)&hh[4]  = *(const float4*)(hp + 4);
    *(float4*)&hh[8]  = *(const float4*)(hp + 8);
    *(float4*)&hh[12] = *(const float4*)(hp + 12);

    float o0 = s_b2[0], o1 = s_b2[1], o2 = s_b2[2], o3 = s_b2[3];
#pragma unroll
    for (int j = 0; j < 32; j++) {
        float a0 = s_b1[j], a1 = 0.f;
#pragma unroll
        for (int q = 0; q < 2; q++) {
            const float4 wa = *(const float4*)&s_d1[j * 16 + q * 4];
            const float4 wb = *(const float4*)&s_d1[j * 16 + 8 + q * 4];
            a0 = fmaf(wa.x, hh[q*4+0], fmaf(wa.y, hh[q*4+1], fmaf(wa.z, hh[q*4+2], fmaf(wa.w, hh[q*4+3], a0))));
            a1 = fmaf(wb.x, hh[8+q*4+0], fmaf(wb.y, hh[8+q*4+1], fmaf(wb.z, hh[8+q*4+2], fmaf(wb.w, hh[8+q*4+3], a1))));
        }
        const float d = mytanh(a0 + a1);
        o0 = fmaf(s_d2[j],      d, o0);
        o1 = fmaf(s_d2[32 + j], d, o1);
        o2 = fmaf(s_d2[64 + j], d, o2);
        o3 = fmaf(s_d2[96 + j], d, o3);
    }
    *(float4*)(out_x + (size_t)e * 4) = make_float4(o0, o1, o2, o3);
}

// ============================================================================
extern "C" void kernel_launch(void* const* d_in, const int* in_sizes, int n_in,
                              void* d_out, int out_size) {
    const float* u_in   = (const float*)d_in[0];
    const float* x_in   = (const float*)d_in[1];
    const float* pu_W1  = (const float*)d_in[2];
    const float* pu_b1  = (const float*)d_in[3];
    const float* pu_W2  = (const float*)d_in[4];
    const float* pu_b2  = (const float*)d_in[5];
    const float* px_W1  = (const float*)d_in[6];
    const float* px_b1  = (const float*)d_in[7];
    const float* px_W2  = (const float*)d_in[8];
    const float* px_b2  = (const float*)d_in[9];
    const float* W_ih   = (const float*)d_in[10];
    const float* b_ih   = (const float*)d_in[11];
    const float* W_hh   = (const float*)d_in[12];
    const float* b_hh   = (const float*)d_in[13];
    const float* dec_W1 = (const float*)d_in[14];
    const float* dec_b1 = (const float*)d_in[15];
    const float* dec_W2 = (const float*)d_in[16];
    const float* dec_b2 = (const float*)d_in[17];

    float* out_x = (float*)d_out;                          // [L,B,4]
    float* out_h = (float*)d_out + (size_t)L_ * B_ * 4;    // [L,B,16]

    k1_gates<<<NE / 256, 256>>>(u_in, x_in, pu_W1, pu_b1, pu_W2, pu_b2,
                                px_W1, px_b1, px_W2, px_b2, W_ih, b_ih);
    k2_recur<<<(B_ + BPC - 1) / BPC, NT2>>>(W_hh, b_hh, out_h);
    k3_dec<<<NE / 256, 256>>>(dec_W1, dec_b1, dec_W2, dec_b2, out_h, out_x);
}

// round 4
// speedup vs baseline: 2.8213x; 1.3922x over previous
#include <cuda_runtime.h>
#include <cstdint>

typedef unsigned long long u64;

#define L_ 1024
#define B_ 2048
#define NE (L_ * B_)

// scratch: input-to-hidden gate projections [L*B][48]
__device__ float g_gates[(size_t)NE * 48];

__device__ __forceinline__ float ex2f(float x) {
    float y; asm("ex2.approx.f32 %0, %1;" : "=f"(y) : "f"(x)); return y;
}
__device__ __forceinline__ float rcpf(float x) {
    float y; asm("rcp.approx.f32 %0, %1;" : "=f"(y) : "f"(x)); return y;
}
__device__ __forceinline__ float sigf(float x) {
    return rcpf(1.0f + ex2f(-1.4426950408889634f * x));
}
__device__ __forceinline__ float mytanh(float x) {
    return fmaf(2.0f, sigf(2.0f * x), -1.0f);
}

// ---- packed f32x2 helpers (FFMA2 path, PTX-only on sm_103a) ----
__device__ __forceinline__ u64 pk2(float lo, float hi) {
    u64 r; asm("mov.b64 %0, {%1, %2};" : "=l"(r) : "f"(lo), "f"(hi)); return r;
}
__device__ __forceinline__ void upk2(float& lo, float& hi, u64 v) {
    asm("mov.b64 {%0, %1}, %2;" : "=f"(lo), "=f"(hi) : "l"(v));
}
__device__ __forceinline__ u64 ffma2(u64 a, u64 b, u64 c) {
    u64 d; asm("fma.rn.f32x2 %0, %1, %2, %3;" : "=l"(d) : "l"(a), "l"(b), "l"(c)); return d;
}
__device__ __forceinline__ u64 fmul2(u64 a, u64 b) {
    u64 d; asm("mul.rn.f32x2 %0, %1, %2;" : "=l"(d) : "l"(a), "l"(b)); return d;
}

// ============================================================================
// K1: pre-MLPs + W_ih projection — 2 elements/thread, f32x2 channel pairs.
// LDS amortized over 2 elements; FFMA2 halves fma-pipe cycles.
// ============================================================================
__global__ void __launch_bounds__(256) k1_gates(
    const float* __restrict__ u_in, const float* __restrict__ x_in,
    const float* __restrict__ pu_W1, const float* __restrict__ pu_b1,
    const float* __restrict__ pu_W2, const float* __restrict__ pu_b2,
    const float* __restrict__ px_W1, const float* __restrict__ px_b1,
    const float* __restrict__ px_W2, const float* __restrict__ px_b2,
    const float* __restrict__ W_ih, const float* __restrict__ b_ih)
{
    __shared__ __align__(16) float s_pu1[64], s_px1[64];       // [c][i] row-major
    __shared__ __align__(16) float s_pu2T[256], s_px2T[256];   // [k][c] transposed
    __shared__ __align__(16) float s_wT[32 * 48];              // [d][g] transposed
    __shared__ __align__(16) float s_bih[48];
    __shared__ __align__(8)  float s_bu1[16], s_bu2[16], s_bx1[16], s_bx2[16];

    const int tid = threadIdx.x;
    for (int i = tid; i < 64;  i += 256) { s_pu1[i] = pu_W1[i]; s_px1[i] = px_W1[i]; }
    for (int i = tid; i < 256; i += 256) {
        s_pu2T[(i & 15) * 16 + (i >> 4)] = pu_W2[i];
        s_px2T[(i & 15) * 16 + (i >> 4)] = px_W2[i];
    }
    for (int i = tid; i < 1536; i += 256) s_wT[(i & 31) * 48 + (i >> 5)] = W_ih[i];
    if (tid < 48) s_bih[tid] = b_ih[tid];
    if (tid < 16) { s_bu1[tid] = pu_b1[tid]; s_bu2[tid] = pu_b2[tid];
                    s_bx1[tid] = px_b1[tid]; s_bx2[tid] = px_b2[tid]; }
    __syncthreads();

    const int e0 = blockIdx.x * 512 + tid;   // NE divisible by 512
    const int e1 = e0 + 256;
    const float4 uA = *(const float4*)(u_in + (size_t)e0 * 4);
    const float4 uB = *(const float4*)(u_in + (size_t)e1 * 4);
    const float4 xA = *(const float4*)(x_in + (size_t)e0 * 4);
    const float4 xB = *(const float4*)(x_in + (size_t)e1 * 4);

    // ---- preprocess layer 1 (scalar; tiny) ----
    float t1a[16], t1b[16], t2a[16], t2b[16];
#pragma unroll
    for (int c = 0; c < 16; c++) {
        const float4 wu = *(const float4*)&s_pu1[c * 4];
        const float4 wx = *(const float4*)&s_px1[c * 4];
        const float bu = s_bu1[c], bx = s_bx1[c];
        t1a[c] = mytanh(fmaf(wu.x, uA.x, fmaf(wu.y, uA.y, fmaf(wu.z, uA.z, fmaf(wu.w, uA.w, bu)))));
        t1b[c] = mytanh(fmaf(wu.x, uB.x, fmaf(wu.y, uB.y, fmaf(wu.z, uB.z, fmaf(wu.w, uB.w, bu)))));
        t2a[c] = mytanh(fmaf(wx.x, xA.x, fmaf(wx.y, xA.y, fmaf(wx.z, xA.z, fmaf(wx.w, xA.w, bx)))));
        t2b[c] = mytanh(fmaf(wx.x, xB.x, fmaf(wx.y, xB.y, fmaf(wx.z, xB.z, fmaf(wx.w, xB.w, bx)))));
    }

    // ---- preprocess layer 2: channel-pair f32x2, weights shared by both elems ----
    u64 ueA[8], ueB[8], xeA[8], xeB[8];
#pragma unroll
    for (int j = 0; j < 8; j++) {
        const u64 bu = *(const u64*)&s_bu2[2 * j];
        const u64 bx = *(const u64*)&s_bx2[2 * j];
        ueA[j] = bu; ueB[j] = bu; xeA[j] = bx; xeB[j] = bx;
    }
#pragma unroll
    for (int k = 0; k < 16; k++) {
        const u64 dA1 = pk2(t1a[k], t1a[k]);
        const u64 dB1 = pk2(t1b[k], t1b[k]);
        const u64 dA2 = pk2(t2a[k], t2a[k]);
        const u64 dB2 = pk2(t2b[k], t2b[k]);
        const ulonglong2* ru = (const ulonglong2*)&s_pu2T[k * 16];
        const ulonglong2* rx = (const ulonglong2*)&s_px2T[k * 16];
#pragma unroll
        for (int q = 0; q < 4; q++) {
            const ulonglong2 wu = ru[q];
            const ulonglong2 wx = rx[q];
            ueA[2*q]   = ffma2(wu.x, dA1, ueA[2*q]);
            ueA[2*q+1] = ffma2(wu.y, dA1, ueA[2*q+1]);
            ueB[2*q]   = ffma2(wu.x, dB1, ueB[2*q]);
            ueB[2*q+1] = ffma2(wu.y, dB1, ueB[2*q+1]);
            xeA[2*q]   = ffma2(wx.x, dA2, xeA[2*q]);
            xeA[2*q+1] = ffma2(wx.y, dA2, xeA[2*q+1]);
            xeB[2*q]   = ffma2(wx.x, dB2, xeB[2*q]);
            xeB[2*q+1] = ffma2(wx.y, dB2, xeB[2*q+1]);
        }
    }
    float ue0[16], ue1[16], xe0[16], xe1[16];
#pragma unroll
    for (int j = 0; j < 8; j++) {
        upk2(ue0[2*j], ue0[2*j+1], ueA[j]);
        upk2(ue1[2*j], ue1[2*j+1], ueB[j]);
        upk2(xe0[2*j], xe0[2*j+1], xeA[j]);
        upk2(xe1[2*j], xe1[2*j+1], xeB[j]);
    }
#pragma unroll
    for (int c = 0; c < 16; c++) {
        ue0[c] = mytanh(ue0[c]); ue1[c] = mytanh(ue1[c]);
        xe0[c] = mytanh(xe0[c]); xe1[c] = mytanh(xe1[c]);
    }

    // ---- gates: 48 outputs as 24 f32x2 pairs per element ----
    u64 accA[24], accB[24];
#pragma unroll
    for (int j = 0; j < 24; j++) {
        const u64 bb = *(const u64*)&s_bih[2 * j];
        accA[j] = bb; accB[j] = bb;
    }
#pragma unroll
    for (int k = 0; k < 32; k++) {
        const float a0 = (k < 16) ? ue0[k] : xe0[k - 16];
        const float a1 = (k < 16) ? ue1[k] : xe1[k - 16];
        const u64 aa0 = pk2(a0, a0);
        const u64 aa1 = pk2(a1, a1);
        const ulonglong2* row = (const ulonglong2*)&s_wT[k * 48];
#pragma unroll
        for (int i = 0; i < 12; i++) {
            const ulonglong2 w = row[i];
            accA[2*i]   = ffma2(w.x, aa0, accA[2*i]);
            accA[2*i+1] = ffma2(w.y, aa0, accA[2*i+1]);
            accB[2*i]   = ffma2(w.x, aa1, accB[2*i]);
            accB[2*i+1] = ffma2(w.y, aa1, accB[2*i+1]);
        }
    }
    float* gpA = g_gates + (size_t)e0 * 48;
    float* gpB = g_gates + (size_t)e1 * 48;
#pragma unroll
    for (int i = 0; i < 12; i++) {
        ((ulonglong2*)gpA)[i] = make_ulonglong2(accA[2*i], accA[2*i+1]);
        ((ulonglong2*)gpB)[i] = make_ulonglong2(accB[2*i], accB[2*i+1]);
    }
}

// ============================================================================
// K2: GRU recurrence + fused decoder. 8-deep gate prefetch ring, f32x2 dots.
// Decoder consumes the hh exchange of the *previous* step (= h_all[l-1]),
// filling the issue slots idle during the recurrence dependency chain.
// ============================================================================
#define BPC 14
#define NT2 (BPC * 16)

__global__ void __launch_bounds__(NT2, 1) k2_recur(
    const float* __restrict__ W_hh, const float* __restrict__ b_hh,
    const float* __restrict__ dec_W1, const float* __restrict__ dec_b1,
    const float* __restrict__ dec_W2, const float* __restrict__ dec_b2,
    float* __restrict__ out_h, float* __restrict__ out_x)
{
    __shared__ __align__(16) float s_h[2][BPC][16];
    const int tid = threadIdx.x, lane = tid & 15, g = tid >> 4;
    const int b = blockIdx.x * BPC + g;
    const bool active = (b < B_);
    const int bb = active ? b : (B_ - 1);

    // W_hh rows as packed k-pairs
    u64 vrp[8], vzp[8], vnp[8];
#pragma unroll
    for (int j = 0; j < 8; j++) {
        vrp[j] = *(const u64*)&W_hh[lane * 16 + 2 * j];
        vzp[j] = *(const u64*)&W_hh[(16 + lane) * 16 + 2 * j];
        vnp[j] = *(const u64*)&W_hh[(32 + lane) * 16 + 2 * j];
    }
    const float bhr = b_hh[lane], bhz = b_hh[16 + lane], bhn = b_hh[32 + lane];

    // decoder weights: lane owns hidden rows 2*lane, 2*lane+1
    u64 wd0[8], wd1[8];
#pragma unroll
    for (int j = 0; j < 8; j++) {
        wd0[j] = *(const u64*)&dec_W1[(2 * lane) * 16 + 2 * j];
        wd1[j] = *(const u64*)&dec_W1[(2 * lane + 1) * 16 + 2 * j];
    }
    const float db1_0 = dec_b1[2 * lane], db1_1 = dec_b1[2 * lane + 1];
    u64 w2p[4];
#pragma unroll
    for (int o = 0; o < 4; o++) w2p[o] = *(const u64*)&dec_W2[o * 32 + 2 * lane];
    const float db2 = dec_b2[lane & 3];

    s_h[0][g][lane] = 0.f;
    s_h[1][g][lane] = 0.f;
    __syncthreads();

    const float* gb = g_gates + (size_t)bb * 48;
    const size_t lstride = (size_t)B_ * 48;

    // 8-deep gate prefetch ring
    float cr[8], cz[8], cn[8], nr[8], nz[8], nn[8];
#pragma unroll
    for (int j = 0; j < 8; j++) {
        const float* gp = gb + (size_t)j * lstride;
        cr[j] = gp[lane]; cz[j] = gp[16 + lane]; cn[j] = gp[32 + lane];
    }

    for (int blk = 0; blk < L_ / 8; blk++) {
#pragma unroll
        for (int j = 0; j < 8; j++) {
            const int l = blk * 8 + j;
            if (blk < L_ / 8 - 1) {
                const float* gp = gb + (size_t)(l + 8) * lstride;
                nr[j] = gp[lane]; nz[j] = gp[16 + lane]; nn[j] = gp[32 + lane];
            }
            const int p = j & 1;   // blk*8 even → (l&1)==(j&1)
            const ulonglong2* sh = (const ulonglong2*)s_h[p][g];
            const ulonglong2 q0 = sh[0], q1 = sh[1], q2 = sh[2], q3 = sh[3];
            const u64 hhp[8] = {q0.x, q0.y, q1.x, q1.y, q2.x, q2.y, q3.x, q3.y};
            const float h_prev = s_h[p][g][lane];
            if (active) out_h[((size_t)l * B_ + bb) * 16 + lane] = h_prev;

            // gh = W_hh @ h + b_hh via FFMA2
            u64 ar = pk2(bhr, 0.f), az = pk2(bhz, 0.f), an = pk2(bhn, 0.f);
#pragma unroll
            for (int k = 0; k < 8; k++) {
                ar = ffma2(vrp[k], hhp[k], ar);
                az = ffma2(vzp[k], hhp[k], az);
                an = ffma2(vnp[k], hhp[k], an);
            }
            float rl, rh, zl, zh, nl, nh;
            upk2(rl, rh, ar); upk2(zl, zh, az); upk2(nl, nh, an);
            const float r = sigf(cr[j] + (rl + rh));
            const float z = sigf(cz[j] + (zl + zh));
            const float n = mytanh(fmaf(r, nl + nh, cn[j]));
            const float h_new = fmaf(z, h_prev - n, n);
            s_h[1 - p][g][lane] = h_new;

            // ---- decoder on hhp == h_all[l-1]  →  out_x[l-1]  (skip l==0) ----
            u64 aD0 = pk2(db1_0, 0.f), aD1 = pk2(db1_1, 0.f);
#pragma unroll
            for (int k = 0; k < 8; k++) {
                aD0 = ffma2(wd0[k], hhp[k], aD0);
                aD1 = ffma2(wd1[k], hhp[k], aD1);
            }
            float d0l, d0h, d1l, d1h;
            upk2(d0l, d0h, aD0); upk2(d1l, d1h, aD1);
            const float d0 = mytanh(d0l + d0h);
            const float d1 = mytanh(d1l + d1h);
            const u64 dpk = pk2(d0, d1);
            float pp0, pp1, pp2, pp3;
            { float lo, hi;
              upk2(lo, hi, fmul2(w2p[0], dpk)); pp0 = lo + hi;
              upk2(lo, hi, fmul2(w2p[1], dpk)); pp1 = lo + hi;
              upk2(lo, hi, fmul2(w2p[2], dpk)); pp2 = lo + hi;
              upk2(lo, hi, fmul2(w2p[3], dpk)); pp3 = lo + hi; }
            // select-merge butterfly: 5 shfls reduce 4 values over 16 lanes
            float q01  = (lane & 1) ? pp1 : pp0;
            float q01b = (lane & 1) ? pp0 : pp1;
            q01 += __shfl_xor_sync(0xffffffffu, q01b, 1);
            float q23  = (lane & 1) ? pp3 : pp2;
            float q23b = (lane & 1) ? pp2 : pp3;
            q23 += __shfl_xor_sync(0xffffffffu, q23b, 1);
            float qq  = (lane & 2) ? q23 : q01;
            float qqb = (lane & 2) ? q01 : q23;
            qq += __shfl_xor_sync(0xffffffffu, qqb, 2);
            qq += __shfl_xor_sync(0xffffffffu, qq, 4);
            qq += __shfl_xor_sync(0xffffffffu, qq, 8);
            if (l > 0 && active && lane < 4)
                out_x[((size_t)(l - 1) * B_ + bb) * 4 + lane] = qq + db2;

            __syncwarp();
        }
#pragma unroll
        for (int j = 0; j < 8; j++) { cr[j] = nr[j]; cz[j] = nz[j]; cn[j] = nn[j]; }
    }

    // ---- tail: decode final h_new (h_all[L-1], sitting in s_h[0]) ----
    {
        const ulonglong2* sh = (const ulonglong2*)s_h[0][g];
        const ulonglong2 q0 = sh[0], q1 = sh[1], q2 = sh[2], q3 = sh[3];
        const u64 hhp[8] = {q0.x, q0.y, q1.x, q1.y, q2.x, q2.y, q3.x, q3.y};
        u64 aD0 = pk2(db1_0, 0.f), aD1 = pk2(db1_1, 0.f);
#pragma unroll
        for (int k = 0; k < 8; k++) {
            aD0 = ffma2(wd0[k], hhp[k], aD0);
            aD1 = ffma2(wd1[k], hhp[k], aD1);
        }
        float d0l, d0h, d1l, d1h;
        upk2(d0l, d0h, aD0); upk2(d1l, d1h, aD1);
        const float d0 = mytanh(d0l + d0h);
        const float d1 = mytanh(d1l + d1h);
        const u64 dpk = pk2(d0, d1);
        float pp0, pp1, pp2, pp3;
        { float lo, hi;
          upk2(lo, hi, fmul2(w2p[0], dpk)); pp0 = lo + hi;
          upk2(lo, hi, fmul2(w2p[1], dpk)); pp1 = lo + hi;
          upk2(lo, hi, fmul2(w2p[2], dpk)); pp2 = lo + hi;
          upk2(lo, hi, fmul2(w2p[3], dpk)); pp3 = lo + hi; }
        float q01  = (lane & 1) ? pp1 : pp0;
        float q01b = (lane & 1) ? pp0 : pp1;
        q01 += __shfl_xor_sync(0xffffffffu, q01b, 1);
        float q23  = (lane & 1) ? pp3 : pp2;
        float q23b = (lane & 1) ? pp2 : pp3;
        q23 += __shfl_xor_sync(0xffffffffu, q23b, 1);
        float qq  = (lane & 2) ? q23 : q01;
        float qqb = (lane & 2) ? q01 : q23;
        qq += __shfl_xor_sync(0xffffffffu, qqb, 2);
        qq += __shfl_xor_sync(0xffffffffu, qq, 4);
        qq += __shfl_xor_sync(0xffffffffu, qq, 8);
        if (active && lane < 4)
            out_x[((size_t)(L_ - 1) * B_ + bb) * 4 + lane] = qq + db2;
    }
}

// ============================================================================
extern "C" void kernel_launch(void* const* d_in, const int* in_sizes, int n_in,
                              void* d_out, int out_size) {
    const float* u_in   = (const float*)d_in[0];
    const float* x_in   = (const float*)d_in[1];
    const float* pu_W1  = (const float*)d_in[2];
    const float* pu_b1  = (const float*)d_in[3];
    const float* pu_W2  = (const float*)d_in[4];
    const float* pu_b2  = (const float*)d_in[5];
    const float* px_W1  = (const float*)d_in[6];
    const float* px_b1  = (const float*)d_in[7];
    const float* px_W2  = (const float*)d_in[8];
    const float* px_b2  = (const float*)d_in[9];
    const float* W_ih   = (const float*)d_in[10];
    const float* b_ih   = (const float*)d_in[11];
    const float* W_hh   = (const float*)d_in[12];
    const float* b_hh   = (const float*)d_in[13];
    const float* dec_W1 = (const float*)d_in[14];
    const float* dec_b1 = (const float*)d_in[15];
    const float* dec_W2 = (const float*)d_in[16];
    const float* dec_b2 = (const float*)d_in[17];

    float* out_x = (float*)d_out;                          // [L,B,4]
    float* out_h = (float*)d_out + (size_t)L_ * B_ * 4;    // [L,B,16]

    k1_gates<<<NE / 512, 256>>>(u_in, x_in, pu_W1, pu_b1, pu_W2, pu_b2,
                                px_W1, px_b1, px_W2, px_b2, W_ih, b_ih);
    k2_recur<<<(B_ + BPC - 1) / BPC, NT2>>>(W_hh, b_hh,
                                            dec_W1, dec_b1, dec_W2, dec_b2,
                                            out_h, out_x);
}